// round 2
// baseline (speedup 1.0000x reference)
#include <cuda_runtime.h>
#include <math.h>

#define NMAX 20000
#define EMAX 200000
#define GMAX 128
#define DH   32

__device__ float g_h0[NMAX * DH];
__device__ float g_h1[NMAX * DH];
__device__ float g_rh1[EMAX * DH];
__device__ float g_rh2[EMAX * DH];
__device__ float g_Gn[(size_t)NMAX * 1056];   // [N][33][32]: k=0..31 w2-part, k=32 bias-part
__device__ float g_agg[NMAX * DH];
__device__ float g_pooled[GMAX * DH];
__device__ int   g_cnt[NMAX];
__device__ int   g_starts[NMAX + 1];
__device__ int   g_off[NMAX];
__device__ int   g_perm[EMAX];

#define FULLMASK 0xffffffffu

__device__ __forceinline__ float lrelu(float v) { return v > 0.f ? v : 0.01f * v; }

// ---------------- Kernel A: h0 = lrelu(x @ nfc_w + nfc_b) -------------------
__global__ void k_node_in(const float* __restrict__ x, const float* __restrict__ w,
                          const float* __restrict__ b, float* __restrict__ h0, int N) {
    int warp = (blockIdx.x * blockDim.x + threadIdx.x) >> 5;
    int lane = threadIdx.x & 31;
    if (warp >= N) return;
    const float* xr = x + (size_t)warp * 64;
    float x0 = xr[lane];
    float x1 = xr[32 + lane];
    float acc = b[lane];
#pragma unroll
    for (int i = 0; i < 32; i++) {
        float xv = __shfl_sync(FULLMASK, x0, i);
        acc = fmaf(xv, w[i * 32 + lane], acc);
    }
#pragma unroll
    for (int i = 0; i < 32; i++) {
        float xv = __shfl_sync(FULLMASK, x1, i);
        acc = fmaf(xv, w[(32 + i) * 32 + lane], acc);
    }
    h0[warp * 32 + lane] = lrelu(acc);
}

// ---------------- Kernel B: rh_L = relu(edge_attr @ w1_L + b1_L), both layers
__global__ void k_edge_hidden(const float* __restrict__ ea,
                              const float* __restrict__ w1a, const float* __restrict__ b1a,
                              const float* __restrict__ w1b, const float* __restrict__ b1b,
                              float* __restrict__ rh1, float* __restrict__ rh2, int E) {
    int warp = (blockIdx.x * blockDim.x + threadIdx.x) >> 5;
    int lane = threadIdx.x & 31;
    if (warp >= E) return;
    float ev = (lane < 16) ? ea[(size_t)warp * 16 + lane] : 0.f;
    float a1 = b1a[lane];
    float a2 = b1b[lane];
#pragma unroll
    for (int j = 0; j < 16; j++) {
        float v = __shfl_sync(FULLMASK, ev, j);
        a1 = fmaf(v, w1a[j * 32 + lane], a1);
        a2 = fmaf(v, w1b[j * 32 + lane], a2);
    }
    rh1[warp * 32 + lane] = fmaxf(a1, 0.f);
    rh2[warp * 32 + lane] = fmaxf(a2, 0.f);
}

// ---------------- sort edges by src: hist + scan + scatter ------------------
__global__ void k_zero_int(int* __restrict__ p, int total) {
    int i = blockIdx.x * blockDim.x + threadIdx.x;
    if (i < total) p[i] = 0;
}

__global__ void k_hist(const int* __restrict__ ei, int* __restrict__ cnt, int E) {
    int e = blockIdx.x * blockDim.x + threadIdx.x;
    if (e < E) atomicAdd(&cnt[ei[e]], 1);
}

// single CTA raking exclusive scan over N counts -> starts (and off copy)
__global__ void k_scan(const int* __restrict__ cnt, int* __restrict__ starts,
                       int* __restrict__ off, int N, int E) {
    __shared__ int sm[1024];
    int t = threadIdx.x;
    int per = (N + 1023) / 1024;
    int lo = t * per, hi = min(N, lo + per);
    int s = 0;
    for (int i = lo; i < hi; i++) s += cnt[i];
    sm[t] = s;
    __syncthreads();
    int own = s;
#pragma unroll
    for (int o = 1; o < 1024; o <<= 1) {
        int v = (t >= o) ? sm[t - o] : 0;
        __syncthreads();
        sm[t] += v;
        __syncthreads();
    }
    int run = sm[t] - own;  // exclusive prefix of this thread's chunk
    for (int i = lo; i < hi; i++) {
        starts[i] = run;
        off[i] = run;
        run += cnt[i];
    }
    if (t == 0) starts[N] = E;
}

__global__ void k_scatter(const int* __restrict__ ei, int* __restrict__ off,
                          int* __restrict__ perm, int E) {
    int e = blockIdx.x * blockDim.x + threadIdx.x;
    if (e < E) {
        int pos = atomicAdd(&off[ei[e]], 1);
        perm[pos] = e;
    }
}

// ---------------- Kernel C: Gn[n][k][o] and agg init (root + bias) ----------
#define NB 8
__global__ void k_precompute(const float* __restrict__ h,
                             const float* __restrict__ w2, const float* __restrict__ b2,
                             const float* __restrict__ root, const float* __restrict__ bias,
                             float* __restrict__ Gn, float* __restrict__ agg, int N) {
    extern __shared__ float sm[];
    float* Ws    = sm;            // 34*1024
    float* biass = sm + 34816;    // 32
    float* hs    = sm + 34848;    // NB*32

    int tid = threadIdx.x;
    for (int idx = tid; idx < 34 * 1024; idx += 256) {
        float v;
        if (idx < 32768)      v = w2[idx];
        else if (idx < 33792) v = b2[idx - 32768];
        else                  v = root[idx - 33792];
        Ws[idx] = v;
    }
    if (tid < 32) biass[tid] = bias[tid];
    __syncthreads();

    int o  = tid & 31;
    int kk = tid >> 5;
    int k_[5];
#pragma unroll
    for (int s = 0; s < 5; s++) k_[s] = kk + 8 * s;

    int ngroups = (N + NB - 1) / NB;
    for (int grp = blockIdx.x; grp < ngroups; grp += gridDim.x) {
        int nbase = grp * NB;
        for (int j = tid; j < NB * 32; j += 256) {
            int n = nbase + (j >> 5);
            hs[j] = (n < N) ? h[(size_t)n * 32 + (j & 31)] : 0.f;
        }
        __syncthreads();

        float acc[5][NB];
#pragma unroll
        for (int s = 0; s < 5; s++)
#pragma unroll
            for (int nb = 0; nb < NB; nb++) acc[s][nb] = 0.f;

#pragma unroll 4
        for (int i = 0; i < 32; i++) {
            float w2v[5];
#pragma unroll
            for (int s = 0; s < 5; s++)
                w2v[s] = (k_[s] < 34) ? Ws[k_[s] * 1024 + i * 32 + o] : 0.f;
#pragma unroll
            for (int nb = 0; nb < NB; nb++) {
                float hv = hs[nb * 32 + i];
#pragma unroll
                for (int s = 0; s < 5; s++) acc[s][nb] = fmaf(hv, w2v[s], acc[s][nb]);
            }
        }

#pragma unroll
        for (int nb = 0; nb < NB; nb++) {
            int n = nbase + nb;
            if (n >= N) break;
#pragma unroll
            for (int s = 0; s < 5; s++) {
                int k = k_[s];
                if (k < 33) {
                    Gn[(size_t)n * 1056 + k * 32 + o] = acc[s][nb];
                } else if (k == 33) {
                    agg[(size_t)n * 32 + o] = acc[s][nb] + biass[o];
                }
            }
        }
        __syncthreads();
    }
}

// ---------------- Kernel D: warp-per-src-node message + scatter-add ---------
__global__ void k_edge_msg_grouped(const int* __restrict__ starts, const int* __restrict__ perm,
                                   const int* __restrict__ ei, const float* __restrict__ rh,
                                   const float* __restrict__ Gn, float* __restrict__ agg,
                                   int N, int E) {
    int warp = (blockIdx.x * blockDim.x + threadIdx.x) >> 5;
    int lane = threadIdx.x & 31;
    if (warp >= N) return;
    int beg = starts[warp];
    int end = starts[warp + 1];
    if (beg == end) return;

    const float* gp = Gn + (size_t)warp * 1056;
    float g[33];
#pragma unroll
    for (int k = 0; k < 33; k++) g[k] = gp[k * 32 + lane];

    for (int e = beg; e < end; e++) {
        int eid = __ldg(&perm[e]);
        int dst = __ldg(&ei[E + eid]);
        float rv = rh[(size_t)eid * 32 + lane];
        float m0 = g[32];   // bias-part row
        float m1 = 0.f;
#pragma unroll
        for (int k = 0; k < 32; k += 2) {
            m0 = fmaf(__shfl_sync(FULLMASK, rv, k),     g[k],     m0);
            m1 = fmaf(__shfl_sync(FULLMASK, rv, k + 1), g[k + 1], m1);
        }
        atomicAdd(&agg[(size_t)dst * 32 + lane], m0 + m1);
    }
}

// ---------------- Kernel E1: h = lrelu(agg) ---------------------------------
__global__ void k_act(const float* __restrict__ agg, float* __restrict__ h, int total) {
    int idx = blockIdx.x * blockDim.x + threadIdx.x;
    if (idx >= total) return;
    h[idx] = lrelu(agg[idx]);
}

__global__ void k_zero(float* __restrict__ p, int total) {
    int idx = blockIdx.x * blockDim.x + threadIdx.x;
    if (idx < total) p[idx] = 0.f;
}

// ---------------- Kernel E2: atom_embs = lrelu(agg); pool into graphs -------
__global__ void k_act_pool(const float* __restrict__ agg, const int* __restrict__ batch,
                           float* __restrict__ atom_out, float* __restrict__ pooled, int N) {
    int idx = blockIdx.x * blockDim.x + threadIdx.x;
    if (idx >= N * 32) return;
    int n = idx >> 5;
    int o = idx & 31;
    float v = lrelu(agg[idx]);
    atom_out[idx] = v;
    atomicAdd(&pooled[batch[n] * 32 + o], v);
}

// ---------------- Kernel F: normalize pooled rows + final fc ----------------
__global__ void k_final(const float* __restrict__ pooled, const float* __restrict__ fcw,
                        const float* __restrict__ fcb, float* __restrict__ out, int G) {
    int warp = (blockIdx.x * blockDim.x + threadIdx.x) >> 5;
    int lane = threadIdx.x & 31;
    if (warp >= G) return;
    float p = pooled[warp * 32 + lane];
    float ss = p * p;
#pragma unroll
    for (int off = 16; off > 0; off >>= 1) ss += __shfl_xor_sync(FULLMASK, ss, off);
    float nrm = sqrtf(ss);
    float d = fmaxf(nrm, 1e-12f);
    float pn = p / d;
    float acc = fcb[lane];
#pragma unroll
    for (int j = 0; j < 32; j++) {
        float pv = __shfl_sync(FULLMASK, pn, j);
        acc = fmaf(pv, fcw[j * 32 + lane], acc);
    }
    out[warp * 32 + lane] = acc;
}

extern "C" void kernel_launch(void* const* d_in, const int* in_sizes, int n_in,
                              void* d_out, int out_size) {
    const float* x        = (const float*)d_in[0];
    const int*   ei       = (const int*)  d_in[1];
    const float* ea       = (const float*)d_in[2];
    const int*   batch    = (const int*)  d_in[3];
    const float* nfc_w    = (const float*)d_in[5];
    const float* nfc_b    = (const float*)d_in[6];
    const float* e1w1     = (const float*)d_in[7];
    const float* e1b1     = (const float*)d_in[8];
    const float* e1w2     = (const float*)d_in[9];
    const float* e1b2     = (const float*)d_in[10];
    const float* root1    = (const float*)d_in[11];
    const float* bias1    = (const float*)d_in[12];
    const float* e2w1     = (const float*)d_in[13];
    const float* e2b1     = (const float*)d_in[14];
    const float* e2w2     = (const float*)d_in[15];
    const float* e2b2     = (const float*)d_in[16];
    const float* root2    = (const float*)d_in[17];
    const float* bias2    = (const float*)d_in[18];
    const float* fcw      = (const float*)d_in[19];
    const float* fcb      = (const float*)d_in[20];

    int N = in_sizes[0] / 64;
    int E = in_sizes[2] / 16;
    const int G = GMAX;

    float* outp = (float*)d_out;                 // [G,32]
    float* atom_out = (float*)d_out + G * 32;    // [N,32]

    float *h0, *h1, *rh1, *rh2, *Gn, *agg, *pooled;
    int *cnt, *starts, *off, *perm;
    cudaGetSymbolAddress((void**)&h0,     g_h0);
    cudaGetSymbolAddress((void**)&h1,     g_h1);
    cudaGetSymbolAddress((void**)&rh1,    g_rh1);
    cudaGetSymbolAddress((void**)&rh2,    g_rh2);
    cudaGetSymbolAddress((void**)&Gn,     g_Gn);
    cudaGetSymbolAddress((void**)&agg,    g_agg);
    cudaGetSymbolAddress((void**)&pooled, g_pooled);
    cudaGetSymbolAddress((void**)&cnt,    g_cnt);
    cudaGetSymbolAddress((void**)&starts, g_starts);
    cudaGetSymbolAddress((void**)&off,    g_off);
    cudaGetSymbolAddress((void**)&perm,   g_perm);

    const int smemC = (34 * 1024 + 32 + NB * 32) * sizeof(float);
    cudaFuncSetAttribute(k_precompute, cudaFuncAttributeMaxDynamicSharedMemorySize, smemC);

    // node input transform + edge hidden layers
    k_node_in<<<(N + 7) / 8, 256>>>(x, nfc_w, nfc_b, h0, N);
    k_edge_hidden<<<(E + 7) / 8, 256>>>(ea, e1w1, e1b1, e2w1, e2b1, rh1, rh2, E);

    // counting sort of edges by src (reused by both layers)
    k_zero_int<<<(N + 255) / 256, 256>>>(cnt, N);
    k_hist<<<(E + 255) / 256, 256>>>(ei, cnt, E);
    k_scan<<<1, 1024>>>(cnt, starts, off, N, E);
    k_scatter<<<(E + 255) / 256, 256>>>(ei, off, perm, E);

    // ---- layer 1 ----
    k_precompute<<<148, 256, smemC>>>(h0, e1w2, e1b2, root1, bias1, Gn, agg, N);
    k_edge_msg_grouped<<<(N + 7) / 8, 256>>>(starts, perm, ei, rh1, Gn, agg, N, E);
    k_act<<<(N * 32 + 255) / 256, 256>>>(agg, h1, N * 32);

    // ---- layer 2 ----
    k_precompute<<<148, 256, smemC>>>(h1, e2w2, e2b2, root2, bias2, Gn, agg, N);
    k_edge_msg_grouped<<<(N + 7) / 8, 256>>>(starts, perm, ei, rh2, Gn, agg, N, E);

    // pooling + outputs
    k_zero<<<(G * 32 + 255) / 256, 256>>>(pooled, G * 32);
    k_act_pool<<<(N * 32 + 255) / 256, 256>>>(agg, batch, atom_out, pooled, N);
    k_final<<<(G + 3) / 4, 128>>>(pooled, fcw, fcb, outp, G);
}

// round 3
// speedup vs baseline: 1.9651x; 1.9651x over previous
#include <cuda_runtime.h>
#include <cuda_fp16.h>
#include <math.h>

#define NMAX 20000
#define EMAX 200000
#define GMAX 128
#define DH   32

__device__ float   g_h0[NMAX * DH];
__device__ float   g_h1[NMAX * DH];
__device__ __half2 g_G2[(size_t)NMAX * 544];   // [N][17][32] half2: pair p=(2p,2p+1), p=16=(biaspart,0)
__device__ float   g_agg[NMAX * DH];
__device__ float   g_pooled[GMAX * DH];

#define FULLMASK 0xffffffffu

__device__ __forceinline__ float lrelu(float v) { return v > 0.f ? v : 0.01f * v; }

// ---------------- Kernel A: h0 = lrelu(x @ nfc_w + nfc_b) -------------------
__global__ void k_node_in(const float* __restrict__ x, const float* __restrict__ w,
                          const float* __restrict__ b, float* __restrict__ h0, int N) {
    int warp = (blockIdx.x * blockDim.x + threadIdx.x) >> 5;
    int lane = threadIdx.x & 31;
    if (warp >= N) return;
    const float* xr = x + (size_t)warp * 64;
    float x0 = xr[lane];
    float x1 = xr[32 + lane];
    float acc = b[lane];
#pragma unroll
    for (int i = 0; i < 32; i++) {
        float xv = __shfl_sync(FULLMASK, x0, i);
        acc = fmaf(xv, w[i * 32 + lane], acc);
    }
#pragma unroll
    for (int i = 0; i < 32; i++) {
        float xv = __shfl_sync(FULLMASK, x1, i);
        acc = fmaf(xv, w[(32 + i) * 32 + lane], acc);
    }
    h0[warp * 32 + lane] = lrelu(acc);
}

// ---------------- Kernel C: per-node table G2 (half2 pairs) + agg init ------
// Smem Ws rows: k=0..31 = w2, 32 = b2, 33 = root. Thread (o=t&31, j=t>>5 in [0,16)):
// computes k=2j and 2j+1 for NB nodes; warps j==0/j==1 additionally compute k=32/33.
#define NB 8
__global__ void k_precompute(const float* __restrict__ h,
                             const float* __restrict__ w2, const float* __restrict__ b2,
                             const float* __restrict__ root, const float* __restrict__ bias,
                             __half2* __restrict__ G2, float* __restrict__ agg, int N) {
    extern __shared__ float sm[];
    float* Ws    = sm;            // 34*1024
    float* biass = sm + 34816;    // 32
    float* hs    = sm + 34848;    // NB*32

    int tid = threadIdx.x;
    for (int idx = tid; idx < 34 * 1024; idx += 512) {
        float v;
        if (idx < 32768)      v = w2[idx];
        else if (idx < 33792) v = b2[idx - 32768];
        else                  v = root[idx - 33792];
        Ws[idx] = v;
    }
    if (tid < 32) biass[tid] = bias[tid];
    __syncthreads();

    int o = tid & 31;
    int j = tid >> 5;            // 0..15
    const float* w0p = Ws + (2 * j) * 1024 + o;
    const float* w1p = Ws + (2 * j + 1) * 1024 + o;
    const float* wxp = Ws + (32 + (j < 2 ? j : 0)) * 1024 + o;  // valid addr always

    int ngroups = (N + NB - 1) / NB;
    for (int grp = blockIdx.x; grp < ngroups; grp += gridDim.x) {
        int nbase = grp * NB;
        for (int q = tid; q < NB * 32; q += 512) {
            int n = nbase + (q >> 5);
            hs[q] = (n < N) ? h[(size_t)n * 32 + (q & 31)] : 0.f;
        }
        __syncthreads();

        float acc0[NB], acc1[NB], accx[NB];
#pragma unroll
        for (int nb = 0; nb < NB; nb++) { acc0[nb] = 0.f; acc1[nb] = 0.f; accx[nb] = 0.f; }

#pragma unroll 4
        for (int i = 0; i < 32; i++) {
            float w0 = w0p[i * 32];
            float w1 = w1p[i * 32];
#pragma unroll
            for (int nb = 0; nb < NB; nb++) {
                float hv = hs[nb * 32 + i];
                acc0[nb] = fmaf(hv, w0, acc0[nb]);
                acc1[nb] = fmaf(hv, w1, acc1[nb]);
            }
        }
        if (j < 2) {
#pragma unroll 4
            for (int i = 0; i < 32; i++) {
                float wx = wxp[i * 32];
#pragma unroll
                for (int nb = 0; nb < NB; nb++)
                    accx[nb] = fmaf(hs[nb * 32 + i], wx, accx[nb]);
            }
        }

#pragma unroll
        for (int nb = 0; nb < NB; nb++) {
            int n = nbase + nb;
            if (n >= N) break;
            G2[(size_t)n * 544 + j * 32 + o] = __floats2half2_rn(acc0[nb], acc1[nb]);
            if (j == 0) G2[(size_t)n * 544 + 512 + o] = __floats2half2_rn(accx[nb], 0.f);
            if (j == 1) agg[(size_t)n * 32 + o] = accx[nb] + biass[o];
        }
        __syncthreads();
    }
}

// ---------------- Kernel D: fused edge hidden MLP + message + scatter-add ---
__global__ void k_edge_msg(const int* __restrict__ ei, const float* __restrict__ ea,
                           const float* __restrict__ w1, const float* __restrict__ b1,
                           const __half2* __restrict__ G2, float* __restrict__ agg, int E) {
    __shared__ float w1s[16 * 32];
    __shared__ float b1s[32];
    int tid = threadIdx.x;
    for (int q = tid; q < 16 * 32; q += 256) w1s[q] = w1[q];
    if (tid < 32) b1s[tid] = b1[tid];
    __syncthreads();

    int warp = (blockIdx.x * blockDim.x + threadIdx.x) >> 5;
    int lane = threadIdx.x & 31;
    if (warp >= E) return;

    int src = __ldg(&ei[warp]);
    int dst = __ldg(&ei[E + warp]);
    float eav = (lane < 16) ? __ldg(&ea[(size_t)warp * 16 + lane]) : 0.f;

    float a = b1s[lane];
#pragma unroll
    for (int jj = 0; jj < 16; jj++)
        a = fmaf(__shfl_sync(FULLMASK, eav, jj), w1s[jj * 32 + lane], a);
    float rv = fmaxf(a, 0.f);

    const __half2* gp = G2 + (size_t)src * 544;
    float2 fb = __half22float2(__ldg(&gp[512 + lane]));
    float m0 = fb.x;
    float m1 = 0.f;
#pragma unroll
    for (int kk = 0; kk < 16; kk++) {
        float2 f = __half22float2(__ldg(&gp[kk * 32 + lane]));
        m0 = fmaf(__shfl_sync(FULLMASK, rv, 2 * kk),     f.x, m0);
        m1 = fmaf(__shfl_sync(FULLMASK, rv, 2 * kk + 1), f.y, m1);
    }
    atomicAdd(&agg[(size_t)dst * 32 + lane], m0 + m1);
}

// ---------------- Kernel E1: h = lrelu(agg) ---------------------------------
__global__ void k_act(const float* __restrict__ agg, float* __restrict__ h, int total) {
    int idx = blockIdx.x * blockDim.x + threadIdx.x;
    if (idx >= total) return;
    h[idx] = lrelu(agg[idx]);
}

__global__ void k_zero(float* __restrict__ p, int total) {
    int idx = blockIdx.x * blockDim.x + threadIdx.x;
    if (idx < total) p[idx] = 0.f;
}

// ---------------- Kernel E2: atom_embs = lrelu(agg); pool into graphs -------
__global__ void k_act_pool(const float* __restrict__ agg, const int* __restrict__ batch,
                           float* __restrict__ atom_out, float* __restrict__ pooled, int N) {
    int idx = blockIdx.x * blockDim.x + threadIdx.x;
    if (idx >= N * 32) return;
    int n = idx >> 5;
    int o = idx & 31;
    float v = lrelu(agg[idx]);
    atom_out[idx] = v;
    atomicAdd(&pooled[batch[n] * 32 + o], v);
}

// ---------------- Kernel F: normalize pooled rows + final fc ----------------
__global__ void k_final(const float* __restrict__ pooled, const float* __restrict__ fcw,
                        const float* __restrict__ fcb, float* __restrict__ out, int G) {
    int warp = (blockIdx.x * blockDim.x + threadIdx.x) >> 5;
    int lane = threadIdx.x & 31;
    if (warp >= G) return;
    float p = pooled[warp * 32 + lane];
    float ss = p * p;
#pragma unroll
    for (int off = 16; off > 0; off >>= 1) ss += __shfl_xor_sync(FULLMASK, ss, off);
    float nrm = sqrtf(ss);
    float d = fmaxf(nrm, 1e-12f);
    float pn = p / d;
    float acc = fcb[lane];
#pragma unroll
    for (int jj = 0; jj < 32; jj++) {
        float pv = __shfl_sync(FULLMASK, pn, jj);
        acc = fmaf(pv, fcw[jj * 32 + lane], acc);
    }
    out[warp * 32 + lane] = acc;
}

extern "C" void kernel_launch(void* const* d_in, const int* in_sizes, int n_in,
                              void* d_out, int out_size) {
    const float* x        = (const float*)d_in[0];
    const int*   ei       = (const int*)  d_in[1];
    const float* ea       = (const float*)d_in[2];
    const int*   batch    = (const int*)  d_in[3];
    const float* nfc_w    = (const float*)d_in[5];
    const float* nfc_b    = (const float*)d_in[6];
    const float* e1w1     = (const float*)d_in[7];
    const float* e1b1     = (const float*)d_in[8];
    const float* e1w2     = (const float*)d_in[9];
    const float* e1b2     = (const float*)d_in[10];
    const float* root1    = (const float*)d_in[11];
    const float* bias1    = (const float*)d_in[12];
    const float* e2w1     = (const float*)d_in[13];
    const float* e2b1     = (const float*)d_in[14];
    const float* e2w2     = (const float*)d_in[15];
    const float* e2b2     = (const float*)d_in[16];
    const float* root2    = (const float*)d_in[17];
    const float* bias2    = (const float*)d_in[18];
    const float* fcw      = (const float*)d_in[19];
    const float* fcb      = (const float*)d_in[20];

    int N = in_sizes[0] / 64;
    int E = in_sizes[2] / 16;
    const int G = GMAX;

    float* outp = (float*)d_out;                 // [G,32]
    float* atom_out = (float*)d_out + G * 32;    // [N,32]

    float *h0, *h1, *agg, *pooled;
    __half2* G2;
    cudaGetSymbolAddress((void**)&h0,     g_h0);
    cudaGetSymbolAddress((void**)&h1,     g_h1);
    cudaGetSymbolAddress((void**)&G2,     g_G2);
    cudaGetSymbolAddress((void**)&agg,    g_agg);
    cudaGetSymbolAddress((void**)&pooled, g_pooled);

    const int smemC = (34 * 1024 + 32 + NB * 32) * sizeof(float);
    cudaFuncSetAttribute(k_precompute, cudaFuncAttributeMaxDynamicSharedMemorySize, smemC);

    k_node_in<<<(N + 7) / 8, 256>>>(x, nfc_w, nfc_b, h0, N);

    // ---- layer 1 ----
    k_precompute<<<148, 512, smemC>>>(h0, e1w2, e1b2, root1, bias1, G2, agg, N);
    k_edge_msg<<<(E + 7) / 8, 256>>>(ei, ea, e1w1, e1b1, G2, agg, E);
    k_act<<<(N * 32 + 255) / 256, 256>>>(agg, h1, N * 32);

    // ---- layer 2 ----
    k_precompute<<<148, 512, smemC>>>(h1, e2w2, e2b2, root2, bias2, G2, agg, N);
    k_edge_msg<<<(E + 7) / 8, 256>>>(ei, ea, e2w1, e2b1, G2, agg, E);

    // pooling + outputs
    k_zero<<<(G * 32 + 255) / 256, 256>>>(pooled, G * 32);
    k_act_pool<<<(N * 32 + 255) / 256, 256>>>(agg, batch, atom_out, pooled, N);
    k_final<<<(G + 3) / 4, 128>>>(pooled, fcw, fcb, outp, G);
}